// round 16
// baseline (speedup 1.0000x reference)
#include <cuda_runtime.h>
#include <cuda_bf16.h>
#include <cuda_fp16.h>

#define Bb 8
#define Nn 1024
#define Ee 512
#define Hh 8
#define Dd 64
#define NEGV -1000000000.0f
#define SCL2 0.1803368801111204f   // 0.125 * log2(e)

typedef unsigned long long u64;
typedef unsigned int u32;

// ---------------------------------------------------------------------------
// Scratch (device globals; referenced only from device code)
// ---------------------------------------------------------------------------
__device__ unsigned char g_code[Bb*Nn*Nn];

__device__ __half gXs[3][Bb*Nn*Ee];          // inputs single fp16
__device__ __half gWs[4][Ee*Ee];             // weights single fp16

__device__ __half gQh[Bb*Hh*Nn*Dd];          // Q single fp16 [b,h,n,d]
__device__ __half gKh[Bb*Hh*Nn*Dd];          // K single fp16 [b,h,n,d]
__device__ __half gVth[Bb*Hh*Dd*Nn];         // V single fp16 transposed [b,h,d,n]
__device__ __half gAh[Bb*Nn*Ee];             // attn out single fp16 (1-term oproj)

// ---------------------------------------------------------------------------
// PTX helpers
// ---------------------------------------------------------------------------
__device__ __forceinline__ unsigned smem_u32(const void* p) {
    unsigned a;
    asm("{ .reg .u64 t; cvta.to.shared.u64 t, %1; cvt.u32.u64 %0, t; }"
        : "=r"(a) : "l"(p));
    return a;
}
__device__ __forceinline__ void cpasync16(unsigned dst, const void* src) {
    asm volatile("cp.async.ca.shared.global [%0], [%1], 16;" :: "r"(dst), "l"(src));
}
__device__ __forceinline__ void cpcommit() {
    asm volatile("cp.async.commit_group;" ::: "memory");
}
template<int N> __device__ __forceinline__ void cpwait() {
    asm volatile("cp.async.wait_group %0;" :: "n"(N) : "memory");
}
__device__ __forceinline__ void mma16816h(float* c, const u32* a, const u32* b) {
    asm volatile("mma.sync.aligned.m16n8k16.row.col.f32.f16.f16.f32 "
        "{%0,%1,%2,%3}, {%4,%5,%6,%7}, {%8,%9}, {%0,%1,%2,%3};"
        : "+f"(c[0]), "+f"(c[1]), "+f"(c[2]), "+f"(c[3])
        : "r"(a[0]), "r"(a[1]), "r"(a[2]), "r"(a[3]), "r"(b[0]), "r"(b[1]));
}
__device__ __forceinline__ void ldsm_x4(u32* r, unsigned addr) {
    asm volatile("ldmatrix.sync.aligned.m8n8.x4.shared.b16 {%0,%1,%2,%3}, [%4];"
        : "=r"(r[0]), "=r"(r[1]), "=r"(r[2]), "=r"(r[3]) : "r"(addr));
}
__device__ __forceinline__ void ldsm_x2(u32* r, unsigned addr) {
    asm volatile("ldmatrix.sync.aligned.m8n8.x2.shared.b16 {%0,%1}, [%2];"
        : "=r"(r[0]), "=r"(r[1]) : "r"(addr));
}
__device__ __forceinline__ float ex2(float x) {
    float y; asm("ex2.approx.f32 %0, %1;" : "=f"(y) : "f"(x)); return y;
}
__device__ __forceinline__ u32 packhf(float lo, float hi) {
    __half2 t = __floats2half2_rn(lo, hi);
    return *(u32*)&t;
}
__device__ __forceinline__ float2 h2ff(u32 v) {
    __half2 t; *(u32*)&t = v;
    return __half22float2(t);
}

// ---------------------------------------------------------------------------
// Fused prologue (high-MLP): code 16 elems/thread, X/W 4xfloat4/thread
// ---------------------------------------------------------------------------
__device__ __forceinline__ unsigned char code_one(float d, int mk, int i, int j) {
    if (mk == 0) return (unsigned char)255;
    if (i == 0 || j == 0) return (unsigned char)0;
    unsigned char c = 0;
    c += (d >= 0.2f); c += (d >= 0.3f); c += (d >= 0.4f); c += (d >= 0.5f);
    c += (d >= 0.6f); c += (d >= 0.7f); c += (d >= 0.8f); c += (d >= 0.9f);
    return c;
}

#define PREP_CODE_BLOCKS 2048     // 16 elems/thread
#define PREP_X_BLOCKS 1024        // 16 floats/thread
#define PREP_W_BLOCKS 64
#define PREP_TOTAL (PREP_CODE_BLOCKS + 3 * PREP_X_BLOCKS + 4 * PREP_W_BLOCKS)

__global__ __launch_bounds__(256) void prep_kernel(
    const float* __restrict__ dist, const int* __restrict__ mask,
    const float* __restrict__ xq, const float* __restrict__ xk,
    const float* __restrict__ xv,
    const float* __restrict__ w0, const float* __restrict__ w1,
    const float* __restrict__ w2, const float* __restrict__ w3)
{
    int bx = blockIdx.x;
    int tid = threadIdx.x;
    if (bx < PREP_CODE_BLOCKS) {
        int t = bx * 256 + tid;
        int base = t * 16;                      // row length 1024 % 16 == 0
        int rem = base & (Nn*Nn - 1);
        int i = rem >> 10;
        int j0 = rem & (Nn - 1);
        float4 dv[4];
        int4 mv[4];
        #pragma unroll
        for (int s = 0; s < 4; s++) dv[s] = *(const float4*)(dist + base + s * 4);
        #pragma unroll
        for (int s = 0; s < 4; s++) mv[s] = *(const int4*)(mask + base + s * 4);
        uint4 pack;
        u32* pw = (u32*)&pack;
        #pragma unroll
        for (int s = 0; s < 4; s++) {
            uchar4 o;
            o.x = code_one(dv[s].x, mv[s].x, i, j0 + s * 4 + 0);
            o.y = code_one(dv[s].y, mv[s].y, i, j0 + s * 4 + 1);
            o.z = code_one(dv[s].z, mv[s].z, i, j0 + s * 4 + 2);
            o.w = code_one(dv[s].w, mv[s].w, i, j0 + s * 4 + 3);
            pw[s] = *(u32*)&o;
        }
        *(uint4*)(g_code + base) = pack;
    } else if (bx < PREP_CODE_BLOCKS + 3 * PREP_X_BLOCKS) {
        int lb = bx - PREP_CODE_BLOCKS;
        int which = lb / PREP_X_BLOCKS;
        int xb = lb - which * PREP_X_BLOCKS;
        const float* src = (which == 0) ? xq : (which == 1) ? xk : xv;
        int t0 = (xb * 256 + tid) * 4;
        u32* h2 = (u32*)gXs[which];
        float4 v[4];
        #pragma unroll
        for (int s = 0; s < 4; s++) v[s] = ((const float4*)src)[t0 + s];
        #pragma unroll
        for (int s = 0; s < 4; s++) {
            h2[2*(t0+s)+0] = packhf(v[s].x, v[s].y);
            h2[2*(t0+s)+1] = packhf(v[s].z, v[s].w);
        }
    } else {
        int lb = bx - PREP_CODE_BLOCKS - 3 * PREP_X_BLOCKS;
        int which = lb / PREP_W_BLOCKS;
        int wb = lb - which * PREP_W_BLOCKS;
        const float* src = (which == 0) ? w0 : (which == 1) ? w1
                          : (which == 2) ? w2 : w3;
        int t0 = (wb * 256 + tid) * 4;
        u32* h2 = (u32*)gWs[which];
        float4 v[4];
        #pragma unroll
        for (int s = 0; s < 4; s++) v[s] = ((const float4*)src)[t0 + s];
        #pragma unroll
        for (int s = 0; s < 4; s++) {
            h2[2*(t0+s)+0] = packhf(v[s].x, v[s].y);
            h2[2*(t0+s)+1] = packhf(v[s].z, v[s].w);
        }
    }
}

// K-chunk 64: rows are 64 halves + 8 pad = 72 (144B stride -> conflict-free)
#define TSTRIDE 72
#define TILE_US (128 * TSTRIDE)

// ---------------------------------------------------------------------------
// gemm_1t: 1-term fp16 GEMM. mode=0 (fused): blockIdx.z=0/1/2 -> Q/K/V proj.
// mode=1: oproj (A=gAh, W=gWs[3], fp32 flat out).  (R15 verbatim)
// ---------------------------------------------------------------------------
#define G1_SMEM_BYTES (4 * TILE_US * 2)      // 73728

__global__ __launch_bounds__(256, 2) void gemm_1t(const float* __restrict__ bias0,
                                                  const float* __restrict__ bias1,
                                                  const float* __restrict__ bias2,
                                                  float* __restrict__ outext,
                                                  int mode) {
    extern __shared__ unsigned short gsm[];
    unsigned sbase = smem_u32(gsm);

    int sel = mode ? 3 : blockIdx.z;
    const __half* Ahg = (sel < 3) ? gXs[sel] : gAh;
    const __half* Wsg = gWs[sel];
    const float* bias = (sel == 0 || sel == 3) ? bias0 : (sel == 1) ? bias1 : bias2;

    int tid = threadIdx.x;
    int wid = tid >> 5, lane = tid & 31;
    int wr = wid >> 2, wc = wid & 3;
    int gid = lane >> 2, tig = lane & 3;
    int m0 = blockIdx.x * 128, n0 = blockIdx.y * 128;

    int rA = lane & 15, kA = (lane >> 4) * 8;
    int rB = lane & 7,  kB = ((lane >> 3) & 1) * 8;

    float c[4][4][4];
    #pragma unroll
    for (int mt = 0; mt < 4; mt++)
        #pragma unroll
        for (int nt = 0; nt < 4; nt++)
            #pragma unroll
            for (int q = 0; q < 4; q++) c[mt][nt][q] = 0.0f;

    auto load_chunk = [&](int kc, int buf) {
        int kb = kc * 64;
        unsigned base = (unsigned)(buf * 2 * TILE_US);
        #pragma unroll
        for (int l = 0; l < 4; l++) {
            int idx = tid + l * 256;
            int row = idx >> 3, c8 = (idx & 7) * 8;
            unsigned so = (row * TSTRIDE + c8) * 2;
            cpasync16(sbase + base * 2 + so, Ahg + (m0 + row) * Ee + kb + c8);
            cpasync16(sbase + (base + TILE_US) * 2 + so, Wsg + (n0 + row) * Ee + kb + c8);
        }
        cpcommit();
    };

    load_chunk(0, 0);

    for (int kc = 0; kc < 8; kc++) {
        int buf = kc & 1;
        if (kc < 7) load_chunk(kc + 1, buf ^ 1);
        if (kc < 7) cpwait<1>(); else cpwait<0>();
        __syncthreads();

        unsigned base = (unsigned)(buf * 2 * TILE_US);
        unsigned ah_b = sbase + base * 2;
        unsigned wh_b = sbase + (base + TILE_US) * 2;

        #pragma unroll
        for (int ks = 0; ks < 4; ks++) {
            int k0 = ks * 16;
            u32 bh[4][2];
            #pragma unroll
            for (int nt = 0; nt < 4; nt++) {
                unsigned boff = ((wc * 32 + nt * 8 + rB) * TSTRIDE + k0 + kB) * 2;
                ldsm_x2(bh[nt], wh_b + boff);
            }
            #pragma unroll
            for (int mt = 0; mt < 4; mt++) {
                unsigned aoff = ((wr * 64 + mt * 16 + rA) * TSTRIDE + k0 + kA) * 2;
                u32 ah[4];
                ldsm_x4(ah, ah_b + aoff);
                #pragma unroll
                for (int nt = 0; nt < 4; nt++)
                    mma16816h(c[mt][nt], ah, bh[nt]);
            }
        }
        __syncthreads();
    }

    // Epilogue
    #pragma unroll
    for (int mt = 0; mt < 4; mt++) {
        #pragma unroll
        for (int nt = 0; nt < 4; nt++) {
            int row = m0 + wr * 64 + mt * 16 + gid;
            int col = n0 + wc * 32 + nt * 8 + tig * 2;
            float b0v = bias[col], b1v = bias[col + 1];
            float v00 = c[mt][nt][0] + b0v, v01 = c[mt][nt][1] + b1v;
            float v10 = c[mt][nt][2] + b0v, v11 = c[mt][nt][3] + b1v;
            int b_ = row >> 10, n = row & (Nn - 1);
            int hh = col >> 6, d = col & 63;
            if (sel <= 1) {
                __half* Hp = (sel == 0) ? gQh : gKh;
                int a0 = (((b_ << 3) + hh) * Nn + n) * Dd + d;
                int a1 = a0 + 8 * Dd;
                *(u32*)(Hp + a0) = packhf(v00, v01);
                *(u32*)(Hp + a1) = packhf(v10, v11);
            } else if (sel == 2) {
                int base = ((b_ << 3) + hh) * Dd;
                int i00 = (base + d) * Nn + n;
                int i01 = (base + d + 1) * Nn + n;
                gVth[i00]     = __float2half(v00);
                gVth[i01]     = __float2half(v01);
                gVth[i00 + 8] = __float2half(v10);
                gVth[i01 + 8] = __float2half(v11);
            } else {
                *(float2*)(outext + row * Ee + col) = make_float2(v00, v01);
                *(float2*)(outext + (row + 8) * Ee + col) = make_float2(v10, v11);
            }
        }
    }
}

// ---------------------------------------------------------------------------
// HMMA flash attention: QK 1-term, PV 1-term.
// 4-stage K/V pipeline, ONE __syncthreads per iteration, base-2 softmax.
// (R15 loop body verbatim; only pipeline depth changed 3->4.)
// ---------------------------------------------------------------------------
#define FTS 72
#define FQ_H 0
#define FSTG0 (128 * FTS)
#define FSTG_SZ (2 * 64 * FTS)
#define FV_OFF (64 * FTS)
#define FLASH_SMEM ((FSTG0 + 4 * FSTG_SZ) * 2)   // 92160 bytes

__global__ __launch_bounds__(256, 2) void flash_mma() {
    extern __shared__ unsigned short fsm[];
    unsigned sbase = smem_u32(fsm);

    int rb = blockIdx.x, h = blockIdx.y, b = blockIdx.z;
    int tid = threadIdx.x, wid = tid >> 5, lane = tid & 31;
    int gid = lane >> 2, tig = lane & 3;
    int bh = b * Hh + h;

    const __half* Qhg = gQh + (bh * Nn + rb * 128) * Dd;
    const __half* Khg = gKh + bh * Nn * Dd;
    const __half* Vhg = gVth + bh * Dd * Nn;
    const unsigned char* codeg = g_code + (b * Nn + rb * 128) * Nn;

    int rA = lane & 15, kA = (lane >> 4) * 8;
    int rB = lane & 7,  kB = ((lane >> 3) & 1) * 8;

    auto load_kv = [&](int kb, int s) {
        unsigned stg = (unsigned)(FSTG0 + s * FSTG_SZ);
        #pragma unroll
        for (int l = 0; l < 2; l++) {
            int idx = tid + l * 256;
            int row = idx >> 3, c8 = (idx & 7) * 8;
            unsigned so = (row * FTS + c8) * 2;
            cpasync16(sbase + stg * 2 + so, Khg + (kb * 64 + row) * Dd + c8);
            cpasync16(sbase + (stg + FV_OFF) * 2 + so, Vhg + row * Nn + kb * 64 + c8);
        }
        cpcommit();
    };

    // Prologue: Q + stage0 (group 0), stage1 (group 1), stage2 (group 2)
    #pragma unroll
    for (int l = 0; l < 4; l++) {
        int idx = tid + l * 256;
        int row = idx >> 3, c8 = (idx & 7) * 8;
        cpasync16(sbase + (FQ_H + row * FTS + c8) * 2, Qhg + row * Dd + c8);
    }
    load_kv(0, 0);
    load_kv(1, 1);
    load_kv(2, 2);

    unsigned qh_base = sbase + ((FQ_H + (wid * 16 + rA) * FTS + kA) * 2);

    float co[8][4];
    #pragma unroll
    for (int dt = 0; dt < 8; dt++)
        #pragma unroll
        for (int q = 0; q < 4; q++) co[dt][q] = 0.0f;
    float m0r = -1e30f, m1r = -1e30f, l0r = 0.0f, l1r = 0.0f;

    int crow0 = wid * 16 + gid;
    const unsigned char* cp0 = codeg + crow0 * Nn + tig * 2;
    const unsigned char* cp1 = codeg + (crow0 + 8) * Nn + tig * 2;

    for (int kb = 0; kb < 16; kb++) {
        // groups loaded through min(kb+2, 15); need group kb complete
        if (kb < 14) cpwait<2>();
        else if (kb == 14) cpwait<1>();
        else cpwait<0>();
        __syncthreads();                          // single barrier per iteration
        if (kb < 13) load_kv(kb + 3, (kb + 3) & 3);  // stage (kb-1)&3: read in kb-1

        unsigned short cw0[8], cw1[8];
        #pragma unroll
        for (int nt = 0; nt < 8; nt++) {
            cw0[nt] = *(const unsigned short*)(cp0 + kb * 64 + nt * 8);
            cw1[nt] = *(const unsigned short*)(cp1 + kb * 64 + nt * 8);
        }

        unsigned stg = (unsigned)(FSTG0 + (kb & 3) * FSTG_SZ);
        unsigned kh_b = sbase + stg * 2;
        unsigned vh_b = sbase + (stg + FV_OFF) * 2;

        // ---- S = Q.K^T ----
        float sc[8][4];
        #pragma unroll
        for (int nt = 0; nt < 8; nt++)
            #pragma unroll
            for (int q = 0; q < 4; q++) sc[nt][q] = 0.0f;

        #pragma unroll
        for (int ks = 0; ks < 4; ks++) {
            u32 ah[4];
            ldsm_x4(ah, qh_base + ks * 32);
            #pragma unroll
            for (int nt = 0; nt < 8; nt++) {
                unsigned kaddr = kh_b + ((nt * 8 + rB) * FTS + ks * 16 + kB) * 2;
                u32 bh2[2];
                ldsm_x2(bh2, kaddr);
                mma16816h(sc[nt], ah, bh2);
            }
        }

        // ---- mask + scale (log2 domain) ----
        #pragma unroll
        for (int nt = 0; nt < 8; nt++) {
            sc[nt][0] = ((unsigned)h >= (cw0[nt] & 255u)) ? sc[nt][0] * SCL2 : NEGV;
            sc[nt][1] = ((unsigned)h >= (cw0[nt] >> 8))   ? sc[nt][1] * SCL2 : NEGV;
            sc[nt][2] = ((unsigned)h >= (cw1[nt] & 255u)) ? sc[nt][2] * SCL2 : NEGV;
            sc[nt][3] = ((unsigned)h >= (cw1[nt] >> 8))   ? sc[nt][3] * SCL2 : NEGV;
        }

        // ---- online softmax (base 2) ----
        float rm0 = -1e30f, rm1 = -1e30f;
        #pragma unroll
        for (int nt = 0; nt < 8; nt++) {
            rm0 = fmaxf(rm0, fmaxf(sc[nt][0], sc[nt][1]));
            rm1 = fmaxf(rm1, fmaxf(sc[nt][2], sc[nt][3]));
        }
        rm0 = fmaxf(rm0, __shfl_xor_sync(0xffffffffu, rm0, 1));
        rm0 = fmaxf(rm0, __shfl_xor_sync(0xffffffffu, rm0, 2));
        rm1 = fmaxf(rm1, __shfl_xor_sync(0xffffffffu, rm1, 1));
        rm1 = fmaxf(rm1, __shfl_xor_sync(0xffffffffu, rm1, 2));
        float mn0 = fmaxf(m0r, rm0), mn1 = fmaxf(m1r, rm1);
        float corr0 = ex2(m0r - mn0), corr1 = ex2(m1r - mn1);
        m0r = mn0; m1r = mn1;

        float ps0 = 0.0f, ps1 = 0.0f;
        #pragma unroll
        for (int nt = 0; nt < 8; nt++) {
            sc[nt][0] = ex2(sc[nt][0] - mn0);
            sc[nt][1] = ex2(sc[nt][1] - mn0);
            sc[nt][2] = ex2(sc[nt][2] - mn1);
            sc[nt][3] = ex2(sc[nt][3] - mn1);
            ps0 += sc[nt][0] + sc[nt][1];
            ps1 += sc[nt][2] + sc[nt][3];
        }
        ps0 += __shfl_xor_sync(0xffffffffu, ps0, 1);
        ps0 += __shfl_xor_sync(0xffffffffu, ps0, 2);
        ps1 += __shfl_xor_sync(0xffffffffu, ps1, 1);
        ps1 += __shfl_xor_sync(0xffffffffu, ps1, 2);
        l0r = l0r * corr0 + ps0;
        l1r = l1r * corr1 + ps1;

        #pragma unroll
        for (int dt = 0; dt < 8; dt++) {
            co[dt][0] *= corr0; co[dt][1] *= corr0;
            co[dt][2] *= corr1; co[dt][3] *= corr1;
        }

        // ---- O += P.V ----
        #pragma unroll
        for (int kc = 0; kc < 4; kc++) {
            u32 pah[4];
            pah[0] = packhf(sc[2*kc][0],   sc[2*kc][1]);
            pah[1] = packhf(sc[2*kc][2],   sc[2*kc][3]);
            pah[2] = packhf(sc[2*kc+1][0], sc[2*kc+1][1]);
            pah[3] = packhf(sc[2*kc+1][2], sc[2*kc+1][3]);
            #pragma unroll
            for (int dt = 0; dt < 8; dt++) {
                unsigned vaddr = vh_b + ((dt * 8 + rB) * FTS + kc * 16 + kB) * 2;
                u32 vh2[2];
                ldsm_x2(vh2, vaddr);
                mma16816h(co[dt], pah, vh2);
            }
        }
    }

    // ---- epilogue: O / l -> gAh single fp16 ----
    float inv0 = 1.0f / l0r, inv1 = 1.0f / l1r;
    int nrow = rb * 128 + wid * 16 + gid;
    int a0base = ((b << 10) + nrow) * Ee + (h << 6);
    int a1base = a0base + 8 * Ee;
    #pragma unroll
    for (int dt = 0; dt < 8; dt++) {
        int d = dt * 8 + tig * 2;
        *(u32*)(gAh + a0base + d) = packhf(co[dt][0] * inv0, co[dt][1] * inv0);
        *(u32*)(gAh + a1base + d) = packhf(co[dt][2] * inv1, co[dt][3] * inv1);
    }
}

// ---------------------------------------------------------------------------
extern "C" void kernel_launch(void* const* d_in, const int* in_sizes, int n_in,
                              void* d_out, int out_size) {
    const float* query = (const float*)d_in[0];
    const float* key   = (const float*)d_in[1];
    const float* value = (const float*)d_in[2];
    const float* dist  = (const float*)d_in[3];
    const int*   mask  = (const int*)d_in[4];
    const float* Wq = (const float*)d_in[5];
    const float* bq = (const float*)d_in[6];
    const float* Wk = (const float*)d_in[7];
    const float* bk = (const float*)d_in[8];
    const float* Wv = (const float*)d_in[9];
    const float* bv = (const float*)d_in[10];
    const float* Wo = (const float*)d_in[11];
    const float* bo = (const float*)d_in[12];
    float* out = (float*)d_out;

    cudaFuncSetAttribute(gemm_1t, cudaFuncAttributeMaxDynamicSharedMemorySize, G1_SMEM_BYTES);
    cudaFuncSetAttribute(flash_mma, cudaFuncAttributeMaxDynamicSharedMemorySize, FLASH_SMEM);

    // 1) fused prologue: mask codes + fp16 conversions (high MLP)
    prep_kernel<<<PREP_TOTAL, 256>>>(dist, mask, query, key, value, Wq, Wk, Wv, Wo);

    // 2) fused Q/K/V projections (1-term, chunk-64)
    gemm_1t<<<dim3((Bb * Nn) / 128, Ee / 128, 3), 256, G1_SMEM_BYTES>>>(
        bq, bk, bv, nullptr, 0);

    // 3) flash attention (4-stage, single-sync)
    flash_mma<<<dim3(Nn / 128, Hh, Bb), 256, FLASH_SMEM>>>();

    // 4) output projection (1-term, chunk-64)
    gemm_1t<<<dim3((Bb * Nn) / 128, Ee / 128, 1), 256, G1_SMEM_BYTES>>>(
        bo, nullptr, nullptr, out, 1);
}

// round 17
// speedup vs baseline: 1.0051x; 1.0051x over previous
#include <cuda_runtime.h>
#include <cuda_bf16.h>
#include <cuda_fp16.h>

#define Bb 8
#define Nn 1024
#define Ee 512
#define Hh 8
#define Dd 64
#define NEGV -1000000000.0f
#define SCL2 0.1803368801111204f   // 0.125 * log2(e)

typedef unsigned long long u64;
typedef unsigned int u32;

// ---------------------------------------------------------------------------
// Scratch (device globals; referenced only from device code)
// ---------------------------------------------------------------------------
__device__ unsigned char g_code[Bb*Nn*Nn];

__device__ __half gXs[3][Bb*Nn*Ee];          // inputs single fp16
__device__ __half gWs[4][Ee*Ee];             // weights single fp16

__device__ __half gQh[Bb*Hh*Nn*Dd];          // Q single fp16 [b,h,n,d]
__device__ __half gKh[Bb*Hh*Nn*Dd];          // K single fp16 [b,h,n,d]
__device__ __half gVth[Bb*Hh*Dd*Nn];         // V single fp16 transposed [b,h,d,n]
__device__ __half gAh[Bb*Nn*Ee];             // attn out single fp16 (1-term oproj)

// ---------------------------------------------------------------------------
// PTX helpers
// ---------------------------------------------------------------------------
__device__ __forceinline__ unsigned smem_u32(const void* p) {
    unsigned a;
    asm("{ .reg .u64 t; cvta.to.shared.u64 t, %1; cvt.u32.u64 %0, t; }"
        : "=r"(a) : "l"(p));
    return a;
}
__device__ __forceinline__ void cpasync16(unsigned dst, const void* src) {
    asm volatile("cp.async.ca.shared.global [%0], [%1], 16;" :: "r"(dst), "l"(src));
}
__device__ __forceinline__ void cpcommit() {
    asm volatile("cp.async.commit_group;" ::: "memory");
}
template<int N> __device__ __forceinline__ void cpwait() {
    asm volatile("cp.async.wait_group %0;" :: "n"(N) : "memory");
}
__device__ __forceinline__ void mma16816h(float* c, const u32* a, const u32* b) {
    asm volatile("mma.sync.aligned.m16n8k16.row.col.f32.f16.f16.f32 "
        "{%0,%1,%2,%3}, {%4,%5,%6,%7}, {%8,%9}, {%0,%1,%2,%3};"
        : "+f"(c[0]), "+f"(c[1]), "+f"(c[2]), "+f"(c[3])
        : "r"(a[0]), "r"(a[1]), "r"(a[2]), "r"(a[3]), "r"(b[0]), "r"(b[1]));
}
__device__ __forceinline__ void ldsm_x4(u32* r, unsigned addr) {
    asm volatile("ldmatrix.sync.aligned.m8n8.x4.shared.b16 {%0,%1,%2,%3}, [%4];"
        : "=r"(r[0]), "=r"(r[1]), "=r"(r[2]), "=r"(r[3]) : "r"(addr));
}
__device__ __forceinline__ void ldsm_x2(u32* r, unsigned addr) {
    asm volatile("ldmatrix.sync.aligned.m8n8.x2.shared.b16 {%0,%1}, [%2];"
        : "=r"(r[0]), "=r"(r[1]) : "r"(addr));
}
__device__ __forceinline__ float ex2(float x) {
    float y; asm("ex2.approx.f32 %0, %1;" : "=f"(y) : "f"(x)); return y;
}
__device__ __forceinline__ u32 packhf(float lo, float hi) {
    __half2 t = __floats2half2_rn(lo, hi);
    return *(u32*)&t;
}
__device__ __forceinline__ float2 h2ff(u32 v) {
    __half2 t; *(u32*)&t = v;
    return __half22float2(t);
}

// ---------------------------------------------------------------------------
// Fused prologue (high-MLP, R16 version): code 16 elems/thread, X/W 4xfloat4
// ---------------------------------------------------------------------------
__device__ __forceinline__ unsigned char code_one(float d, int mk, int i, int j) {
    if (mk == 0) return (unsigned char)255;
    if (i == 0 || j == 0) return (unsigned char)0;
    unsigned char c = 0;
    c += (d >= 0.2f); c += (d >= 0.3f); c += (d >= 0.4f); c += (d >= 0.5f);
    c += (d >= 0.6f); c += (d >= 0.7f); c += (d >= 0.8f); c += (d >= 0.9f);
    return c;
}

#define PREP_CODE_BLOCKS 2048     // 16 elems/thread
#define PREP_X_BLOCKS 1024        // 16 floats/thread
#define PREP_W_BLOCKS 64
#define PREP_TOTAL (PREP_CODE_BLOCKS + 3 * PREP_X_BLOCKS + 4 * PREP_W_BLOCKS)

__global__ __launch_bounds__(256) void prep_kernel(
    const float* __restrict__ dist, const int* __restrict__ mask,
    const float* __restrict__ xq, const float* __restrict__ xk,
    const float* __restrict__ xv,
    const float* __restrict__ w0, const float* __restrict__ w1,
    const float* __restrict__ w2, const float* __restrict__ w3)
{
    int bx = blockIdx.x;
    int tid = threadIdx.x;
    if (bx < PREP_CODE_BLOCKS) {
        int t = bx * 256 + tid;
        int base = t * 16;
        int rem = base & (Nn*Nn - 1);
        int i = rem >> 10;
        int j0 = rem & (Nn - 1);
        float4 dv[4];
        int4 mv[4];
        #pragma unroll
        for (int s = 0; s < 4; s++) dv[s] = *(const float4*)(dist + base + s * 4);
        #pragma unroll
        for (int s = 0; s < 4; s++) mv[s] = *(const int4*)(mask + base + s * 4);
        uint4 pack;
        u32* pw = (u32*)&pack;
        #pragma unroll
        for (int s = 0; s < 4; s++) {
            uchar4 o;
            o.x = code_one(dv[s].x, mv[s].x, i, j0 + s * 4 + 0);
            o.y = code_one(dv[s].y, mv[s].y, i, j0 + s * 4 + 1);
            o.z = code_one(dv[s].z, mv[s].z, i, j0 + s * 4 + 2);
            o.w = code_one(dv[s].w, mv[s].w, i, j0 + s * 4 + 3);
            pw[s] = *(u32*)&o;
        }
        *(uint4*)(g_code + base) = pack;
    } else if (bx < PREP_CODE_BLOCKS + 3 * PREP_X_BLOCKS) {
        int lb = bx - PREP_CODE_BLOCKS;
        int which = lb / PREP_X_BLOCKS;
        int xb = lb - which * PREP_X_BLOCKS;
        const float* src = (which == 0) ? xq : (which == 1) ? xk : xv;
        int t0 = (xb * 256 + tid) * 4;
        u32* h2 = (u32*)gXs[which];
        float4 v[4];
        #pragma unroll
        for (int s = 0; s < 4; s++) v[s] = ((const float4*)src)[t0 + s];
        #pragma unroll
        for (int s = 0; s < 4; s++) {
            h2[2*(t0+s)+0] = packhf(v[s].x, v[s].y);
            h2[2*(t0+s)+1] = packhf(v[s].z, v[s].w);
        }
    } else {
        int lb = bx - PREP_CODE_BLOCKS - 3 * PREP_X_BLOCKS;
        int which = lb / PREP_W_BLOCKS;
        int wb = lb - which * PREP_W_BLOCKS;
        const float* src = (which == 0) ? w0 : (which == 1) ? w1
                          : (which == 2) ? w2 : w3;
        int t0 = (wb * 256 + tid) * 4;
        u32* h2 = (u32*)gWs[which];
        float4 v[4];
        #pragma unroll
        for (int s = 0; s < 4; s++) v[s] = ((const float4*)src)[t0 + s];
        #pragma unroll
        for (int s = 0; s < 4; s++) {
            h2[2*(t0+s)+0] = packhf(v[s].x, v[s].y);
            h2[2*(t0+s)+1] = packhf(v[s].z, v[s].w);
        }
    }
}

// K-chunk 64: rows are 64 halves + 8 pad = 72 (144B stride -> conflict-free)
#define TSTRIDE 72
#define TILE_US (128 * TSTRIDE)

// ---------------------------------------------------------------------------
// gemm_1t: 1-term fp16 GEMM. mode=0 (fused): blockIdx.z=0/1/2 -> Q/K/V proj.
// mode=1: oproj (A=gAh, W=gWs[3], fp32 flat out).  (R15 verbatim)
// ---------------------------------------------------------------------------
#define G1_SMEM_BYTES (4 * TILE_US * 2)      // 73728

__global__ __launch_bounds__(256, 2) void gemm_1t(const float* __restrict__ bias0,
                                                  const float* __restrict__ bias1,
                                                  const float* __restrict__ bias2,
                                                  float* __restrict__ outext,
                                                  int mode) {
    extern __shared__ unsigned short gsm[];
    unsigned sbase = smem_u32(gsm);

    int sel = mode ? 3 : blockIdx.z;
    const __half* Ahg = (sel < 3) ? gXs[sel] : gAh;
    const __half* Wsg = gWs[sel];
    const float* bias = (sel == 0 || sel == 3) ? bias0 : (sel == 1) ? bias1 : bias2;

    int tid = threadIdx.x;
    int wid = tid >> 5, lane = tid & 31;
    int wr = wid >> 2, wc = wid & 3;
    int gid = lane >> 2, tig = lane & 3;
    int m0 = blockIdx.x * 128, n0 = blockIdx.y * 128;

    int rA = lane & 15, kA = (lane >> 4) * 8;
    int rB = lane & 7,  kB = ((lane >> 3) & 1) * 8;

    float c[4][4][4];
    #pragma unroll
    for (int mt = 0; mt < 4; mt++)
        #pragma unroll
        for (int nt = 0; nt < 4; nt++)
            #pragma unroll
            for (int q = 0; q < 4; q++) c[mt][nt][q] = 0.0f;

    auto load_chunk = [&](int kc, int buf) {
        int kb = kc * 64;
        unsigned base = (unsigned)(buf * 2 * TILE_US);
        #pragma unroll
        for (int l = 0; l < 4; l++) {
            int idx = tid + l * 256;
            int row = idx >> 3, c8 = (idx & 7) * 8;
            unsigned so = (row * TSTRIDE + c8) * 2;
            cpasync16(sbase + base * 2 + so, Ahg + (m0 + row) * Ee + kb + c8);
            cpasync16(sbase + (base + TILE_US) * 2 + so, Wsg + (n0 + row) * Ee + kb + c8);
        }
        cpcommit();
    };

    load_chunk(0, 0);

    for (int kc = 0; kc < 8; kc++) {
        int buf = kc & 1;
        if (kc < 7) load_chunk(kc + 1, buf ^ 1);
        if (kc < 7) cpwait<1>(); else cpwait<0>();
        __syncthreads();

        unsigned base = (unsigned)(buf * 2 * TILE_US);
        unsigned ah_b = sbase + base * 2;
        unsigned wh_b = sbase + (base + TILE_US) * 2;

        #pragma unroll
        for (int ks = 0; ks < 4; ks++) {
            int k0 = ks * 16;
            u32 bh[4][2];
            #pragma unroll
            for (int nt = 0; nt < 4; nt++) {
                unsigned boff = ((wc * 32 + nt * 8 + rB) * TSTRIDE + k0 + kB) * 2;
                ldsm_x2(bh[nt], wh_b + boff);
            }
            #pragma unroll
            for (int mt = 0; mt < 4; mt++) {
                unsigned aoff = ((wr * 64 + mt * 16 + rA) * TSTRIDE + k0 + kA) * 2;
                u32 ah[4];
                ldsm_x4(ah, ah_b + aoff);
                #pragma unroll
                for (int nt = 0; nt < 4; nt++)
                    mma16816h(c[mt][nt], ah, bh[nt]);
            }
        }
        __syncthreads();
    }

    // Epilogue
    #pragma unroll
    for (int mt = 0; mt < 4; mt++) {
        #pragma unroll
        for (int nt = 0; nt < 4; nt++) {
            int row = m0 + wr * 64 + mt * 16 + gid;
            int col = n0 + wc * 32 + nt * 8 + tig * 2;
            float b0v = bias[col], b1v = bias[col + 1];
            float v00 = c[mt][nt][0] + b0v, v01 = c[mt][nt][1] + b1v;
            float v10 = c[mt][nt][2] + b0v, v11 = c[mt][nt][3] + b1v;
            int b_ = row >> 10, n = row & (Nn - 1);
            int hh = col >> 6, d = col & 63;
            if (sel <= 1) {
                __half* Hp = (sel == 0) ? gQh : gKh;
                int a0 = (((b_ << 3) + hh) * Nn + n) * Dd + d;
                int a1 = a0 + 8 * Dd;
                *(u32*)(Hp + a0) = packhf(v00, v01);
                *(u32*)(Hp + a1) = packhf(v10, v11);
            } else if (sel == 2) {
                int base = ((b_ << 3) + hh) * Dd;
                int i00 = (base + d) * Nn + n;
                int i01 = (base + d + 1) * Nn + n;
                gVth[i00]     = __float2half(v00);
                gVth[i01]     = __float2half(v01);
                gVth[i00 + 8] = __float2half(v10);
                gVth[i01 + 8] = __float2half(v11);
            } else {
                *(float2*)(outext + row * Ee + col) = make_float2(v00, v01);
                *(float2*)(outext + (row + 8) * Ee + col) = make_float2(v10, v11);
            }
        }
    }
}

// ---------------------------------------------------------------------------
// HMMA flash attention: QK 1-term, PV 1-term.
// 3-stage K/V pipeline, ONE __syncthreads per iteration, base-2 softmax.
// (R15 version, byte-identical — reverting R16's 4-stage experiment.)
// ---------------------------------------------------------------------------
#define FTS 72
#define FQ_H 0
#define FSTG0 (128 * FTS)
#define FSTG_SZ (2 * 64 * FTS)
#define FV_OFF (64 * FTS)
#define FLASH_SMEM ((FSTG0 + 3 * FSTG_SZ) * 2)   // 73728 bytes

__global__ __launch_bounds__(256, 2) void flash_mma() {
    extern __shared__ unsigned short fsm[];
    unsigned sbase = smem_u32(fsm);

    int rb = blockIdx.x, h = blockIdx.y, b = blockIdx.z;
    int tid = threadIdx.x, wid = tid >> 5, lane = tid & 31;
    int gid = lane >> 2, tig = lane & 3;
    int bh = b * Hh + h;

    const __half* Qhg = gQh + (bh * Nn + rb * 128) * Dd;
    const __half* Khg = gKh + bh * Nn * Dd;
    const __half* Vhg = gVth + bh * Dd * Nn;
    const unsigned char* codeg = g_code + (b * Nn + rb * 128) * Nn;

    int rA = lane & 15, kA = (lane >> 4) * 8;
    int rB = lane & 7,  kB = ((lane >> 3) & 1) * 8;

    auto load_kv = [&](int kb, int s) {
        unsigned stg = (unsigned)(FSTG0 + s * FSTG_SZ);
        #pragma unroll
        for (int l = 0; l < 2; l++) {
            int idx = tid + l * 256;
            int row = idx >> 3, c8 = (idx & 7) * 8;
            unsigned so = (row * FTS + c8) * 2;
            cpasync16(sbase + stg * 2 + so, Khg + (kb * 64 + row) * Dd + c8);
            cpasync16(sbase + (stg + FV_OFF) * 2 + so, Vhg + row * Nn + kb * 64 + c8);
        }
        cpcommit();
    };

    // Prologue: Q + stage0 (group 0), stage1 (group 1)
    #pragma unroll
    for (int l = 0; l < 4; l++) {
        int idx = tid + l * 256;
        int row = idx >> 3, c8 = (idx & 7) * 8;
        cpasync16(sbase + (FQ_H + row * FTS + c8) * 2, Qhg + row * Dd + c8);
    }
    load_kv(0, 0);
    load_kv(1, 1);

    unsigned qh_base = sbase + ((FQ_H + (wid * 16 + rA) * FTS + kA) * 2);

    float co[8][4];
    #pragma unroll
    for (int dt = 0; dt < 8; dt++)
        #pragma unroll
        for (int q = 0; q < 4; q++) co[dt][q] = 0.0f;
    float m0r = -1e30f, m1r = -1e30f, l0r = 0.0f, l1r = 0.0f;

    int crow0 = wid * 16 + gid;
    const unsigned char* cp0 = codeg + crow0 * Nn + tig * 2;
    const unsigned char* cp1 = codeg + (crow0 + 8) * Nn + tig * 2;

    for (int kb = 0; kb < 16; kb++) {
        if (kb < 15) cpwait<1>(); else cpwait<0>();
        __syncthreads();
        if (kb < 14) load_kv(kb + 2, (kb + 2) % 3);

        unsigned short cw0[8], cw1[8];
        #pragma unroll
        for (int nt = 0; nt < 8; nt++) {
            cw0[nt] = *(const unsigned short*)(cp0 + kb * 64 + nt * 8);
            cw1[nt] = *(const unsigned short*)(cp1 + kb * 64 + nt * 8);
        }

        unsigned stg = (unsigned)(FSTG0 + (kb % 3) * FSTG_SZ);
        unsigned kh_b = sbase + stg * 2;
        unsigned vh_b = sbase + (stg + FV_OFF) * 2;

        // ---- S = Q.K^T ----
        float sc[8][4];
        #pragma unroll
        for (int nt = 0; nt < 8; nt++)
            #pragma unroll
            for (int q = 0; q < 4; q++) sc[nt][q] = 0.0f;

        #pragma unroll
        for (int ks = 0; ks < 4; ks++) {
            u32 ah[4];
            ldsm_x4(ah, qh_base + ks * 32);
            #pragma unroll
            for (int nt = 0; nt < 8; nt++) {
                unsigned kaddr = kh_b + ((nt * 8 + rB) * FTS + ks * 16 + kB) * 2;
                u32 bh2[2];
                ldsm_x2(bh2, kaddr);
                mma16816h(sc[nt], ah, bh2);
            }
        }

        // ---- mask + scale (log2 domain) ----
        #pragma unroll
        for (int nt = 0; nt < 8; nt++) {
            sc[nt][0] = ((unsigned)h >= (cw0[nt] & 255u)) ? sc[nt][0] * SCL2 : NEGV;
            sc[nt][1] = ((unsigned)h >= (cw0[nt] >> 8))   ? sc[nt][1] * SCL2 : NEGV;
            sc[nt][2] = ((unsigned)h >= (cw1[nt] & 255u)) ? sc[nt][2] * SCL2 : NEGV;
            sc[nt][3] = ((unsigned)h >= (cw1[nt] >> 8))   ? sc[nt][3] * SCL2 : NEGV;
        }

        // ---- online softmax (base 2) ----
        float rm0 = -1e30f, rm1 = -1e30f;
        #pragma unroll
        for (int nt = 0; nt < 8; nt++) {
            rm0 = fmaxf(rm0, fmaxf(sc[nt][0], sc[nt][1]));
            rm1 = fmaxf(rm1, fmaxf(sc[nt][2], sc[nt][3]));
        }
        rm0 = fmaxf(rm0, __shfl_xor_sync(0xffffffffu, rm0, 1));
        rm0 = fmaxf(rm0, __shfl_xor_sync(0xffffffffu, rm0, 2));
        rm1 = fmaxf(rm1, __shfl_xor_sync(0xffffffffu, rm1, 1));
        rm1 = fmaxf(rm1, __shfl_xor_sync(0xffffffffu, rm1, 2));
        float mn0 = fmaxf(m0r, rm0), mn1 = fmaxf(m1r, rm1);
        float corr0 = ex2(m0r - mn0), corr1 = ex2(m1r - mn1);
        m0r = mn0; m1r = mn1;

        float ps0 = 0.0f, ps1 = 0.0f;
        #pragma unroll
        for (int nt = 0; nt < 8; nt++) {
            sc[nt][0] = ex2(sc[nt][0] - mn0);
            sc[nt][1] = ex2(sc[nt][1] - mn0);
            sc[nt][2] = ex2(sc[nt][2] - mn1);
            sc[nt][3] = ex2(sc[nt][3] - mn1);
            ps0 += sc[nt][0] + sc[nt][1];
            ps1 += sc[nt][2] + sc[nt][3];
        }
        ps0 += __shfl_xor_sync(0xffffffffu, ps0, 1);
        ps0 += __shfl_xor_sync(0xffffffffu, ps0, 2);
        ps1 += __shfl_xor_sync(0xffffffffu, ps1, 1);
        ps1 += __shfl_xor_sync(0xffffffffu, ps1, 2);
        l0r = l0r * corr0 + ps0;
        l1r = l1r * corr1 + ps1;

        #pragma unroll
        for (int dt = 0; dt < 8; dt++) {
            co[dt][0] *= corr0; co[dt][1] *= corr0;
            co[dt][2] *= corr1; co[dt][3] *= corr1;
        }

        // ---- O += P.V ----
        #pragma unroll
        for (int kc = 0; kc < 4; kc++) {
            u32 pah[4];
            pah[0] = packhf(sc[2*kc][0],   sc[2*kc][1]);
            pah[1] = packhf(sc[2*kc][2],   sc[2*kc][3]);
            pah[2] = packhf(sc[2*kc+1][0], sc[2*kc+1][1]);
            pah[3] = packhf(sc[2*kc+1][2], sc[2*kc+1][3]);
            #pragma unroll
            for (int dt = 0; dt < 8; dt++) {
                unsigned vaddr = vh_b + ((dt * 8 + rB) * FTS + kc * 16 + kB) * 2;
                u32 vh2[2];
                ldsm_x2(vh2, vaddr);
                mma16816h(co[dt], pah, vh2);
            }
        }
    }

    // ---- epilogue: O / l -> gAh single fp16 ----
    float inv0 = 1.0f / l0r, inv1 = 1.0f / l1r;
    int nrow = rb * 128 + wid * 16 + gid;
    int a0base = ((b << 10) + nrow) * Ee + (h << 6);
    int a1base = a0base + 8 * Ee;
    #pragma unroll
    for (int dt = 0; dt < 8; dt++) {
        int d = dt * 8 + tig * 2;
        *(u32*)(gAh + a0base + d) = packhf(co[dt][0] * inv0, co[dt][1] * inv0);
        *(u32*)(gAh + a1base + d) = packhf(co[dt][2] * inv1, co[dt][3] * inv1);
    }
}

// ---------------------------------------------------------------------------
extern "C" void kernel_launch(void* const* d_in, const int* in_sizes, int n_in,
                              void* d_out, int out_size) {
    const float* query = (const float*)d_in[0];
    const float* key   = (const float*)d_in[1];
    const float* value = (const float*)d_in[2];
    const float* dist  = (const float*)d_in[3];
    const int*   mask  = (const int*)d_in[4];
    const float* Wq = (const float*)d_in[5];
    const float* bq = (const float*)d_in[6];
    const float* Wk = (const float*)d_in[7];
    const float* bk = (const float*)d_in[8];
    const float* Wv = (const float*)d_in[9];
    const float* bv = (const float*)d_in[10];
    const float* Wo = (const float*)d_in[11];
    const float* bo = (const float*)d_in[12];
    float* out = (float*)d_out;

    cudaFuncSetAttribute(gemm_1t, cudaFuncAttributeMaxDynamicSharedMemorySize, G1_SMEM_BYTES);
    cudaFuncSetAttribute(flash_mma, cudaFuncAttributeMaxDynamicSharedMemorySize, FLASH_SMEM);

    // 1) fused prologue: mask codes + fp16 conversions (high MLP)
    prep_kernel<<<PREP_TOTAL, 256>>>(dist, mask, query, key, value, Wq, Wk, Wv, Wo);

    // 2) fused Q/K/V projections (1-term, chunk-64)
    gemm_1t<<<dim3((Bb * Nn) / 128, Ee / 128, 3), 256, G1_SMEM_BYTES>>>(
        bq, bk, bv, nullptr, 0);

    // 3) flash attention (3-stage, single-sync — R15 version)
    flash_mma<<<dim3(Nn / 128, Hh, Bb), 256, FLASH_SMEM>>>();

    // 4) output projection (1-term, chunk-64)
    gemm_1t<<<dim3((Bb * Nn) / 128, Ee / 128, 1), 256, G1_SMEM_BYTES>>>(
        bo, nullptr, nullptr, out, 1);
}